// round 14
// baseline (speedup 1.0000x reference)
#include <cuda_runtime.h>
#include <cuda_bf16.h>
#include <math.h>

// Problem constants
#define T_  256
#define B_  128
#define H_  1024
#define L_  4
#define MTOT (T_ * B_)   // 32768

#define NBLK 128
#define NTHR 256

// Scratch
__device__ float g_P[(size_t)MTOT * H_];
__device__ __align__(16) __nv_bfloat16 g_hb[2][2][(size_t)B_ * H_]; // [buf][hi/lo]

// bf16 hi/lo split scratch for the tensor-core precompute GEMM
__device__ __nv_bfloat16 g_Xhi[(size_t)MTOT * H_];
__device__ __nv_bfloat16 g_Xlo[(size_t)MTOT * H_];
__device__ __nv_bfloat16 g_Whi[(size_t)H_ * H_];
__device__ __nv_bfloat16 g_Wlo[(size_t)H_ * H_];

// grid barrier state (proven R9 mechanism)
__device__ volatile unsigned g_bar_gen = 0;
__device__ unsigned g_bar_cnt = 0;

__device__ __forceinline__ void grid_barrier()
{
    __syncthreads();
    if (threadIdx.x == 0) {
        unsigned gen = g_bar_gen;
        __threadfence();
        if (atomicAdd(&g_bar_cnt, 1) == NBLK - 1) {
            atomicExch(&g_bar_cnt, 0);
            __threadfence();
            g_bar_gen = gen + 1;
        } else {
            while (g_bar_gen == gen) { }
            __threadfence();
        }
    }
    __syncthreads();
}

// ---------------------------------------------------------------------------
// fp32 -> (hi, lo) bf16 split.
// ---------------------------------------------------------------------------
__global__ __launch_bounds__(256) void split_bf16(
    const float* __restrict__ src,
    __nv_bfloat16* __restrict__ hi, __nv_bfloat16* __restrict__ lo, int n4)
{
    int i = blockIdx.x * 256 + threadIdx.x;
    if (i >= n4) return;
    float4 v = ((const float4*)src)[i];
    __nv_bfloat16 h0 = __float2bfloat16_rn(v.x);
    __nv_bfloat16 h1 = __float2bfloat16_rn(v.y);
    __nv_bfloat16 h2 = __float2bfloat16_rn(v.z);
    __nv_bfloat16 h3 = __float2bfloat16_rn(v.w);
    __nv_bfloat16 l0 = __float2bfloat16_rn(v.x - __bfloat162float(h0));
    __nv_bfloat16 l1 = __float2bfloat16_rn(v.y - __bfloat162float(h1));
    __nv_bfloat16 l2 = __float2bfloat16_rn(v.z - __bfloat162float(h2));
    __nv_bfloat16 l3 = __float2bfloat16_rn(v.w - __bfloat162float(h3));
    __nv_bfloat162* hp = (__nv_bfloat162*)hi;
    __nv_bfloat162* lp = (__nv_bfloat162*)lo;
    hp[2 * i]     = __nv_bfloat162{h0, h1};
    hp[2 * i + 1] = __nv_bfloat162{h2, h3};
    lp[2 * i]     = __nv_bfloat162{l0, l1};
    lp[2 * i + 1] = __nv_bfloat162{l2, l3};
}

// ---------------------------------------------------------------------------
// helpers
// ---------------------------------------------------------------------------
__device__ __forceinline__ unsigned smem_u32(const void* p)
{
    return (unsigned)__cvta_generic_to_shared(p);
}

__device__ __forceinline__ void ldsm_x4(unsigned addr, unsigned& r0, unsigned& r1,
                                        unsigned& r2, unsigned& r3)
{
    asm volatile("ldmatrix.sync.aligned.m8n8.x4.shared.b16 {%0,%1,%2,%3}, [%4];"
                 : "=r"(r0), "=r"(r1), "=r"(r2), "=r"(r3) : "r"(addr));
}

__device__ __forceinline__ void mma16816(float* d, const unsigned* a,
                                         unsigned b0, unsigned b1)
{
    asm volatile(
        "mma.sync.aligned.m16n8k16.row.col.f32.bf16.bf16.f32 "
        "{%0,%1,%2,%3},{%4,%5,%6,%7},{%8,%9},{%0,%1,%2,%3};"
        : "+f"(d[0]), "+f"(d[1]), "+f"(d[2]), "+f"(d[3])
        : "r"(a[0]), "r"(a[1]), "r"(a[2]), "r"(a[3]), "r"(b0), "r"(b1));
}

#define CP_ASYNC16(dst_u32, src_ptr) \
    asm volatile("cp.async.ca.shared.global [%0], [%1], 16;" \
                 :: "r"(dst_u32), "l"(src_ptr))
#define CP_COMMIT() asm volatile("cp.async.commit_group;")
#define CP_WAIT(N)  asm volatile("cp.async.wait_group %0;" :: "n"(N))

// ---------------------------------------------------------------------------
// Tensor-core precompute GEMM (unchanged, proven):
//   P = Xhi@Whi^T + Xhi@Wlo^T + Xlo@Whi^T + (bi + bh)
// ---------------------------------------------------------------------------
__global__ __launch_bounds__(256) void gemm_pre_bf16(
    const float* __restrict__ bi, const float* __restrict__ bh)
{
    __shared__ uint4 sA[2][128 * 5];
    __shared__ uint4 sB[2][128 * 5];
    __shared__ float sBias[128];

    const int m0 = blockIdx.y * 128;
    const int n0 = blockIdx.x * 128;
    const int tid = threadIdx.x;
    const int wid = tid >> 5;
    const int lane = tid & 31;
    const int warp_m = wid >> 1;
    const int warp_n = wid & 1;

    if (tid < 128) sBias[tid] = bi[n0 + tid] + bh[n0 + tid];

    const __nv_bfloat16* Aseg[3] = { g_Xhi, g_Xhi, g_Xlo };
    const __nv_bfloat16* Bseg[3] = { g_Whi, g_Wlo, g_Whi };

    const int r0u = tid >> 2;
    const int c0u = tid & 3;
    const size_t aOff0 = (size_t)(m0 + r0u) * H_ + c0u * 8;
    const size_t aOff1 = aOff0 + (size_t)64 * H_;
    const size_t bOff0 = (size_t)(n0 + r0u) * H_ + c0u * 8;
    const size_t bOff1 = bOff0 + (size_t)64 * H_;

    float acc0[8][4], acc1[8][4];
    #pragma unroll
    for (int j = 0; j < 8; j++)
        #pragma unroll
        for (int q = 0; q < 4; q++) { acc0[j][q] = 0.f; acc1[j][q] = 0.f; }

    uint4 pa0 = *(const uint4*)(Aseg[0] + aOff0);
    uint4 pa1 = *(const uint4*)(Aseg[0] + aOff1);
    uint4 pb0 = *(const uint4*)(Bseg[0] + bOff0);
    uint4 pb1 = *(const uint4*)(Bseg[0] + bOff1);

    #pragma unroll 1
    for (int ci = 0; ci < 96; ci++) {
        uint4* bufA = sA[ci & 1];
        uint4* bufB = sB[ci & 1];
        bufA[r0u * 5 + c0u] = pa0;
        bufA[(r0u + 64) * 5 + c0u] = pa1;
        bufB[r0u * 5 + c0u] = pb0;
        bufB[(r0u + 64) * 5 + c0u] = pb1;
        __syncthreads();

        if (ci < 95) {
            const int cn = ci + 1;
            const int sg = cn >> 5;
            const size_t k2 = (size_t)(cn & 31) * 32;
            pa0 = *(const uint4*)(Aseg[sg] + aOff0 + k2);
            pa1 = *(const uint4*)(Aseg[sg] + aOff1 + k2);
            pb0 = *(const uint4*)(Bseg[sg] + bOff0 + k2);
            pb1 = *(const uint4*)(Bseg[sg] + bOff1 + k2);
        }

        const unsigned saA = smem_u32(bufA);
        const unsigned saB = smem_u32(bufB);

        #pragma unroll
        for (int ks = 0; ks < 2; ks++) {
            unsigned a0[4], a1[4];
            {
                const int row = warp_m * 32 + (lane & 7) + ((lane >> 3) & 1) * 8;
                const int cu = ks * 2 + (lane >> 4);
                ldsm_x4(saA + (unsigned)((row * 5 + cu) * 16),
                        a0[0], a0[1], a0[2], a0[3]);
                ldsm_x4(saA + (unsigned)(((row + 16) * 5 + cu) * 16),
                        a1[0], a1[1], a1[2], a1[3]);
            }
            unsigned b[4][4];
            {
                const int rb = warp_n * 64 + (lane & 7) + ((lane >> 4) & 1) * 8;
                const int cu = ks * 2 + ((lane >> 3) & 1);
                #pragma unroll
                for (int g = 0; g < 4; g++)
                    ldsm_x4(saB + (unsigned)(((rb + g * 16) * 5 + cu) * 16),
                            b[g][0], b[g][1], b[g][2], b[g][3]);
            }
            #pragma unroll
            for (int g = 0; g < 4; g++) {
                mma16816(acc0[2 * g],     a0, b[g][0], b[g][1]);
                mma16816(acc0[2 * g + 1], a0, b[g][2], b[g][3]);
                mma16816(acc1[2 * g],     a1, b[g][0], b[g][1]);
                mma16816(acc1[2 * g + 1], a1, b[g][2], b[g][3]);
            }
        }
        __syncthreads();
    }

    const int mrow = m0 + warp_m * 32 + (lane >> 2);
    const int ncol0 = warp_n * 64 + 2 * (lane & 3);
    #pragma unroll
    for (int i = 0; i < 2; i++) {
        const int r = mrow + i * 16;
        #pragma unroll
        for (int j = 0; j < 8; j++) {
            const int cc = ncol0 + j * 8;
            const float b0 = sBias[cc];
            const float b1 = sBias[cc + 1];
            const float* av = (i == 0) ? acc0[j] : acc1[j];
            float2 v0 = make_float2(av[0] + b0, av[1] + b1);
            float2 v1 = make_float2(av[2] + b0, av[3] + b1);
            *(float2*)&g_P[(size_t)r * H_ + n0 + cc] = v0;
            *(float2*)&g_P[(size_t)(r + 8) * H_ + n0 + cc] = v1;
        }
    }
}

// ---------------------------------------------------------------------------
// Kernel 2: persistent TENSOR-CORE recurrence (R9 kernel + arrive/wait split).
// 128 blocks x 256 threads. Block tile: 64 b-rows x 16 n-cols.
//   n0 = 16*(bid>>1), b0 = 64*(bid&1).
// 8 warps = 4 b-groups (16 rows) x 2 k-halves (512 k each). Each warp
// computes BOTH n8-tiles of the block's 16-n width (A fragments reused).
// out = h_hi@Whi^T + h_hi@Wlo^T + h_lo@Whi^T, 6 accumulator chains; the 2
// k-halves are summed via a SMEM reduction. h staged per-warp via cp.async,
// 4-deep pipeline (BK=64, 8 chunks); no __syncthreads in the k-loop.
// NEW vs R9: the per-step grid barrier (same atomic mechanism) is split into
// arrive -> deferred stores (ox, fused Xhi/Xlo split, hn) -> wait, so those
// stores are off the inter-block critical path; barrier skipped on the last
// step (kernel exit is the fence).
// SMEM: W 64 KB + staging 8w x 4buf x 4608 B = 144 KB + reduce 4 KB = 217 KB.
// ---------------------------------------------------------------------------
#define SW_BYTES2  65536
#define SW_SPLIT2  32768
#define SHW_CH     2304                         // per-split per-chunk (16*9*16)
#define SHW_BUFB   4608                         // chunk buf (hi+lo)
#define SHW_WARP   (4 * SHW_BUFB)               // 18432
#define RED_OFF    (SW_BYTES2 + 8 * SHW_WARP)   // 212992
#define RNN3_SMEM  (RED_OFF + 4096)             // 217088

__global__ __launch_bounds__(NTHR, 1) void rnn_seq_mma3(
    const float* __restrict__ hx, const float* __restrict__ Wh,
    float* __restrict__ outx, float* __restrict__ hn)
{
    extern __shared__ char sm[];
    char* sW = sm;                    // [split][u(128)][n(16)] 16B units
    char* sH = sm + SW_BYTES2;        // 8 x per-warp regions (4 bufs each)
    float* sred = (float*)(sm + RED_OFF);

    const int tid = threadIdx.x;
    const int bid = blockIdx.x;
    const int warp = tid >> 5;
    const int lane = tid & 31;

    const int n0  = (bid >> 1) * 16;
    const int b0  = (bid & 1) * 64;
    const int bg  = warp >> 1;          // b-group 0..3
    const int kh  = warp & 1;           // k-half
    const int r0w = b0 + 16 * bg;

    // --- load + split Whh rows n0..n0+15 into SMEM (once per layer) ---
    #pragma unroll
    for (int j = 0; j < 8; j++) {
        int g = tid + 256 * j;        // 0..2047
        int n = g & 15;
        int u = g >> 4;               // 0..127
        const float* src = Wh + (size_t)(n0 + n) * H_ + u * 8;
        float4 f0 = *(const float4*)src;
        float4 f1 = *(const float4*)(src + 4);
        float fv[8] = { f0.x, f0.y, f0.z, f0.w, f1.x, f1.y, f1.z, f1.w };
        union { __nv_bfloat162 b2[4]; uint4 u4; } hi_, lo_;
        #pragma unroll
        for (int q = 0; q < 4; q++) {
            __nv_bfloat16 h0 = __float2bfloat16_rn(fv[2 * q]);
            __nv_bfloat16 h1 = __float2bfloat16_rn(fv[2 * q + 1]);
            hi_.b2[q] = __nv_bfloat162{h0, h1};
            lo_.b2[q] = __nv_bfloat162{
                __float2bfloat16_rn(fv[2 * q] - __bfloat162float(h0)),
                __float2bfloat16_rn(fv[2 * q + 1] - __bfloat162float(h1))};
        }
        int off = (u * 16 + n) * 16;
        *(uint4*)(sW + off) = hi_.u4;
        *(uint4*)(sW + SW_SPLIT2 + off) = lo_.u4;
    }

    // --- init h: g_hb[0] = split(hx) ---
    {
        int gi = bid * NTHR + tid;
        float4 v = ((const float4*)hx)[gi];
        union { __nv_bfloat162 b2[2]; uint2 u; } hi_, lo_;
        __nv_bfloat16 h0 = __float2bfloat16_rn(v.x);
        __nv_bfloat16 h1 = __float2bfloat16_rn(v.y);
        __nv_bfloat16 h2 = __float2bfloat16_rn(v.z);
        __nv_bfloat16 h3 = __float2bfloat16_rn(v.w);
        hi_.b2[0] = __nv_bfloat162{h0, h1};
        hi_.b2[1] = __nv_bfloat162{h2, h3};
        lo_.b2[0] = __nv_bfloat162{
            __float2bfloat16_rn(v.x - __bfloat162float(h0)),
            __float2bfloat16_rn(v.y - __bfloat162float(h1))};
        lo_.b2[1] = __nv_bfloat162{
            __float2bfloat16_rn(v.z - __bfloat162float(h2)),
            __float2bfloat16_rn(v.w - __bfloat162float(h3))};
        ((uint2*)g_hb[0][0])[gi] = hi_.u;
        ((uint2*)g_hb[0][1])[gi] = lo_.u;
    }
    grid_barrier();

    // per-thread constants
    const unsigned swu = smem_u32(sW);
    const unsigned shw = smem_u32(sH) + warp * SHW_WARP;
    const int srow = lane >> 1;                  // staging row 0..15
    const int su0  = (lane & 1) * 4;             // staging unit base 0/4
    const unsigned st_off = (unsigned)((srow * 9 + su0) * 16);
    const int arow = (lane & 7) + ((lane >> 3) & 1) * 8;
    const unsigned bn0 = (unsigned)(lane & 7);
    const unsigned bn1 = bn0 + 8;
    const int mr0 = r0w + (lane >> 2);
    const int mr1 = mr0 + 8;
    const int cc0 = n0 + 2 * (lane & 3);         // n-tile 0; tile 1 = +8

    for (int t = 0; t < T_; t++) {
        const __nv_bfloat16* __restrict__ hhi = g_hb[t & 1][0];
        const __nv_bfloat16* __restrict__ hlo = g_hb[t & 1][1];
        __nv_bfloat16* __restrict__ nhi = g_hb[(t + 1) & 1][0];
        __nv_bfloat16* __restrict__ nlo = g_hb[(t + 1) & 1][1];
        const float* __restrict__ Pt = g_P + (size_t)t * B_ * H_;
        float* __restrict__ ox = outx + (size_t)t * B_ * H_;

        float2 Pv00, Pv01, Pv10, Pv11;
        if (kh == 0) {
            Pv00 = *(const float2*)&Pt[(size_t)mr0 * H_ + cc0];
            Pv01 = *(const float2*)&Pt[(size_t)mr0 * H_ + cc0 + 8];
            Pv10 = *(const float2*)&Pt[(size_t)mr1 * H_ + cc0];
            Pv11 = *(const float2*)&Pt[(size_t)mr1 * H_ + cc0 + 8];
        }

        float aA0[4] = {0,0,0,0}, aB0[4] = {0,0,0,0}, aC0[4] = {0,0,0,0};
        float aA1[4] = {0,0,0,0}, aB1[4] = {0,0,0,0}, aC1[4] = {0,0,0,0};

        // global staging source (this lane): row r0w+srow, k-half kh
        const __nv_bfloat16* ghi =
            hhi + (size_t)(r0w + srow) * H_ + kh * 512 + su0 * 8;
        const __nv_bfloat16* glo =
            hlo + (size_t)(r0w + srow) * H_ + kh * 512 + su0 * 8;

        // prologue: issue chunks 0..2
        #pragma unroll
        for (int pc = 0; pc < 3; pc++) {
            unsigned d = shw + pc * SHW_BUFB + st_off;
            const __nv_bfloat16* s_hi = ghi + pc * 64;
            const __nv_bfloat16* s_lo = glo + pc * 64;
            #pragma unroll
            for (int i = 0; i < 4; i++) {
                CP_ASYNC16(d + i * 16, (const char*)(s_hi + i * 8));
                CP_ASYNC16(d + SHW_CH + i * 16, (const char*)(s_lo + i * 8));
            }
            CP_COMMIT();
        }

        #pragma unroll 1
        for (int kc = 0; kc < 8; kc++) {
            if (kc + 3 < 8) {
                unsigned d = shw + ((kc + 3) & 3) * SHW_BUFB + st_off;
                const __nv_bfloat16* s_hi = ghi + (kc + 3) * 64;
                const __nv_bfloat16* s_lo = glo + (kc + 3) * 64;
                #pragma unroll
                for (int i = 0; i < 4; i++) {
                    CP_ASYNC16(d + i * 16, (const char*)(s_hi + i * 8));
                    CP_ASYNC16(d + SHW_CH + i * 16, (const char*)(s_lo + i * 8));
                }
                CP_COMMIT();
            }
            if (kc <= 4)      { CP_WAIT(3); }
            else if (kc == 5) { CP_WAIT(2); }
            else if (kc == 6) { CP_WAIT(1); }
            else              { CP_WAIT(0); }
            __syncwarp();

            const unsigned ab = shw + (kc & 3) * SHW_BUFB;
            #pragma unroll
            for (int p = 0; p < 2; p++) {
                unsigned ua = (unsigned)(kh * 64 + kc * 8 + p * 4 + (lane >> 3));
                unsigned ba0 = swu + (ua * 16 + bn0) * 16;
                unsigned ba1 = swu + (ua * 16 + bn1) * 16;
                unsigned bh0[4], bl0[4], bh1[4], bl1[4];
                ldsm_x4(ba0, bh0[0], bh0[1], bh0[2], bh0[3]);
                ldsm_x4(ba0 + SW_SPLIT2, bl0[0], bl0[1], bl0[2], bl0[3]);
                ldsm_x4(ba1, bh1[0], bh1[1], bh1[2], bh1[3]);
                ldsm_x4(ba1 + SW_SPLIT2, bl1[0], bl1[1], bl1[2], bl1[3]);
                #pragma unroll
                for (int q = 0; q < 2; q++) {
                    unsigned ahi[4], alo[4];
                    const unsigned cu = (unsigned)(p * 4 + q * 2 + (lane >> 4));
                    const unsigned aaddr = ab + (unsigned)((arow * 9 + cu) * 16);
                    ldsm_x4(aaddr, ahi[0], ahi[1], ahi[2], ahi[3]);
                    ldsm_x4(aaddr + SHW_CH, alo[0], alo[1], alo[2], alo[3]);
                    mma16816(aA0, ahi, bh0[2 * q], bh0[2 * q + 1]);
                    mma16816(aB0, ahi, bl0[2 * q], bl0[2 * q + 1]);
                    mma16816(aC0, alo, bh0[2 * q], bh0[2 * q + 1]);
                    mma16816(aA1, ahi, bh1[2 * q], bh1[2 * q + 1]);
                    mma16816(aB1, ahi, bl1[2 * q], bl1[2 * q + 1]);
                    mma16816(aC1, alo, bh1[2 * q], bh1[2 * q + 1]);
                }
            }
        }

        // combine 3 chains, then reduce the 2 k-halves through SMEM
        float s0[4], s1[4];
        #pragma unroll
        for (int i = 0; i < 4; i++) {
            s0[i] = (aA0[i] + aB0[i]) + aC0[i];
            s1[i] = (aA1[i] + aB1[i]) + aC1[i];
        }
        if (kh == 1) {
            float4* dst = (float4*)&sred[(bg * 32 + lane) * 8];
            dst[0] = make_float4(s0[0], s0[1], s0[2], s0[3]);
            dst[1] = make_float4(s1[0], s1[1], s1[2], s1[3]);
        }
        __syncthreads();

        // epilogue values (kh==0 warps)
        float v00, v01, v10, v11, w00, w01, w10, w11;
        size_t i0 = 0, i1 = 0;
        __nv_bfloat162 hv[4], lv[4];
        if (kh == 0) {
            const float4* srd = (const float4*)&sred[(bg * 32 + lane) * 8];
            float4 r0 = srd[0], r1 = srd[1];
            s0[0] += r0.x; s0[1] += r0.y; s0[2] += r0.z; s0[3] += r0.w;
            s1[0] += r1.x; s1[1] += r1.y; s1[2] += r1.z; s1[3] += r1.w;

            v00 = tanhf(s0[0] + Pv00.x);
            v01 = tanhf(s0[1] + Pv00.y);
            v10 = tanhf(s0[2] + Pv10.x);
            v11 = tanhf(s0[3] + Pv10.y);
            w00 = tanhf(s1[0] + Pv01.x);
            w01 = tanhf(s1[1] + Pv01.y);
            w10 = tanhf(s1[2] + Pv11.x);
            w11 = tanhf(s1[3] + Pv11.y);

            i0 = (size_t)mr0 * H_ + cc0;
            i1 = (size_t)mr1 * H_ + cc0;

            float xs0[4] = { v00, w00, v10, w10 };
            float xs1[4] = { v01, w01, v11, w11 };
            #pragma unroll
            for (int e = 0; e < 4; e++) {
                __nv_bfloat16 hh0 = __float2bfloat16_rn(xs0[e]);
                __nv_bfloat16 hh1 = __float2bfloat16_rn(xs1[e]);
                hv[e] = __nv_bfloat162{hh0, hh1};
                lv[e] = __nv_bfloat162{
                    __float2bfloat16_rn(xs0[e] - __bfloat162float(hh0)),
                    __float2bfloat16_rn(xs1[e] - __bfloat162float(hh1))};
            }

            // critical-path stores: next-step h only
            *(__nv_bfloat162*)&nhi[i0]     = hv[0];
            *(__nv_bfloat162*)&nhi[i0 + 8] = hv[1];
            *(__nv_bfloat162*)&nhi[i1]     = hv[2];
            *(__nv_bfloat162*)&nhi[i1 + 8] = hv[3];
            *(__nv_bfloat162*)&nlo[i0]     = lv[0];
            *(__nv_bfloat162*)&nlo[i0 + 8] = lv[1];
            *(__nv_bfloat162*)&nlo[i1]     = lv[2];
            *(__nv_bfloat162*)&nlo[i1 + 8] = lv[3];
        }

        // ---- barrier ARRIVE (same mechanism as R9, split) ----
        unsigned gen_s = 0;
        bool last_step = (t == T_ - 1);
        if (!last_step) {
            __syncthreads();                // all warps' work for step t done
            if (tid == 0) {
                gen_s = g_bar_gen;
                __threadfence();            // make this block's writes visible
                if (atomicAdd(&g_bar_cnt, 1) == NBLK - 1) {
                    atomicExch(&g_bar_cnt, 0);
                    __threadfence();
                    g_bar_gen = gen_s + 1;  // release
                }
            }
        }

        // ---- deferred stores (overlap with barrier stragglers) ----
        if (kh == 0) {
            const size_t xb = (size_t)t * B_ * H_;
            *(float2*)&ox[i0]     = make_float2(v00, v01);
            *(float2*)&ox[i0 + 8] = make_float2(w00, w01);
            *(float2*)&ox[i1]     = make_float2(v10, v11);
            *(float2*)&ox[i1 + 8] = make_float2(w10, w11);
            *(__nv_bfloat162*)&g_Xhi[xb + i0]     = hv[0];
            *(__nv_bfloat162*)&g_Xhi[xb + i0 + 8] = hv[1];
            *(__nv_bfloat162*)&g_Xhi[xb + i1]     = hv[2];
            *(__nv_bfloat162*)&g_Xhi[xb + i1 + 8] = hv[3];
            *(__nv_bfloat162*)&g_Xlo[xb + i0]     = lv[0];
            *(__nv_bfloat162*)&g_Xlo[xb + i0 + 8] = lv[1];
            *(__nv_bfloat162*)&g_Xlo[xb + i1]     = lv[2];
            *(__nv_bfloat162*)&g_Xlo[xb + i1 + 8] = lv[3];
            if (last_step) {
                *(float2*)&hn[i0]     = make_float2(v00, v01);
                *(float2*)&hn[i0 + 8] = make_float2(w00, w01);
                *(float2*)&hn[i1]     = make_float2(v10, v11);
                *(float2*)&hn[i1 + 8] = make_float2(w10, w11);
            }
        }

        // ---- barrier WAIT ----
        if (!last_step) {
            if (tid == 0) {
                while (g_bar_gen == gen_s) { }
                __threadfence();
            }
            __syncthreads();
        }
    }
}

// ---------------------------------------------------------------------------
// Launch: layer 0: split X; every layer: split W_ih, GEMM, recurrence.
// The recurrence writes the NEXT layer's Xhi/Xlo itself. 13 graph nodes.
// ---------------------------------------------------------------------------
extern "C" void kernel_launch(void* const* d_in, const int* in_sizes, int n_in,
                              void* d_out, int out_size)
{
    const float* inputs = (const float*)d_in[0];   // [T,B,H]
    const float* hxs    = (const float*)d_in[1];   // [L,B,H]
    const float* W_ih   = (const float*)d_in[2];   // [L,H,H]
    const float* b_ih   = (const float*)d_in[3];   // [L,H]
    const float* W_hh   = (const float*)d_in[4];   // [L,H,H]
    const float* b_hh   = (const float*)d_in[5];   // [L,H]

    float* out  = (float*)d_out;
    float* outx = out;                               // [T,B,H]
    float* outh = out + (size_t)T_ * B_ * H_;        // [L,B,H]

    static bool attr_done = false;
    if (!attr_done) {
        cudaFuncSetAttribute(rnn_seq_mma3,
                             cudaFuncAttributeMaxDynamicSharedMemorySize,
                             RNN3_SMEM);
        attr_done = true;
    }

    __nv_bfloat16* xhi; cudaGetSymbolAddress((void**)&xhi, g_Xhi);
    __nv_bfloat16* xlo; cudaGetSymbolAddress((void**)&xlo, g_Xlo);
    __nv_bfloat16* whi; cudaGetSymbolAddress((void**)&whi, g_Whi);
    __nv_bfloat16* wlo; cudaGetSymbolAddress((void**)&wlo, g_Wlo);

    const int nX4 = MTOT * H_ / 4;
    const int nW4 = H_ * H_ / 4;

    dim3 pre_grid(H_ / 128, MTOT / 128);             // (8, 256)

    for (int l = 0; l < L_; l++) {
        if (l == 0)
            split_bf16<<<nX4 / 256, 256>>>(inputs, xhi, xlo, nX4);
        split_bf16<<<nW4 / 256, 256>>>(W_ih + (size_t)l * H_ * H_, whi, wlo, nW4);
        gemm_pre_bf16<<<pre_grid, 256>>>(b_ih + (size_t)l * H_,
                                         b_hh + (size_t)l * H_);
        rnn_seq_mma3<<<NBLK, NTHR, RNN3_SMEM>>>(
            hxs + (size_t)l * B_ * H_,
            W_hh + (size_t)l * H_ * H_,
            outx,
            outh + (size_t)l * B_ * H_);
    }
}

// round 16
// speedup vs baseline: 1.2477x; 1.2477x over previous
#include <cuda_runtime.h>
#include <cuda_bf16.h>
#include <math.h>

// Problem constants
#define T_  256
#define B_  128
#define H_  1024
#define L_  4
#define MTOT (T_ * B_)   // 32768

#define NBLK 128
#define NTHR 256

// Scratch
__device__ float g_P[(size_t)MTOT * H_];
__device__ __align__(16) __nv_bfloat16 g_hb[2][2][(size_t)B_ * H_]; // [buf][hi/lo]

// bf16 hi/lo split scratch
__device__ __nv_bfloat16 g_Xhi[(size_t)MTOT * H_];
__device__ __nv_bfloat16 g_Xlo[(size_t)MTOT * H_];
__device__ __nv_bfloat16 g_Whi[(size_t)H_ * H_];
__device__ __nv_bfloat16 g_Wlo[(size_t)H_ * H_];

// barrier state: one full-grid barrier (init) + 4 per-group barriers
__device__ volatile unsigned g_bar_gen = 0;
__device__ unsigned g_bar_cnt = 0;
__device__ volatile unsigned g_ggen[4 * 32];   // [grp*32], padded
__device__ unsigned g_gcnt[4 * 32];

__device__ __forceinline__ void grid_barrier_full()
{
    __syncthreads();
    if (threadIdx.x == 0) {
        unsigned gen = g_bar_gen;
        __threadfence();
        if (atomicAdd(&g_bar_cnt, 1) == NBLK - 1) {
            atomicExch(&g_bar_cnt, 0);
            __threadfence();
            g_bar_gen = gen + 1;
        } else {
            while (g_bar_gen == gen) { }
            __threadfence();
        }
    }
    __syncthreads();
}

// per-group barrier over 32 blocks — same proven mechanism, smaller scope
__device__ __forceinline__ void grid_barrier_grp(int grp)
{
    __syncthreads();
    if (threadIdx.x == 0) {
        const int idx = grp * 32;
        unsigned gen = g_ggen[idx];
        __threadfence();
        if (atomicAdd(&g_gcnt[idx], 1) == 31) {
            atomicExch(&g_gcnt[idx], 0);
            __threadfence();
            g_ggen[idx] = gen + 1;
        } else {
            while (g_ggen[idx] == gen) { }
            __threadfence();
        }
    }
    __syncthreads();
}

// ---------------------------------------------------------------------------
// fp32 -> (hi, lo) bf16 split.
// ---------------------------------------------------------------------------
__global__ __launch_bounds__(256) void split_bf16(
    const float* __restrict__ src,
    __nv_bfloat16* __restrict__ hi, __nv_bfloat16* __restrict__ lo, int n4)
{
    int i = blockIdx.x * 256 + threadIdx.x;
    if (i >= n4) return;
    float4 v = ((const float4*)src)[i];
    __nv_bfloat16 h0 = __float2bfloat16_rn(v.x);
    __nv_bfloat16 h1 = __float2bfloat16_rn(v.y);
    __nv_bfloat16 h2 = __float2bfloat16_rn(v.z);
    __nv_bfloat16 h3 = __float2bfloat16_rn(v.w);
    __nv_bfloat16 l0 = __float2bfloat16_rn(v.x - __bfloat162float(h0));
    __nv_bfloat16 l1 = __float2bfloat16_rn(v.y - __bfloat162float(h1));
    __nv_bfloat16 l2 = __float2bfloat16_rn(v.z - __bfloat162float(h2));
    __nv_bfloat16 l3 = __float2bfloat16_rn(v.w - __bfloat162float(h3));
    __nv_bfloat162* hp = (__nv_bfloat162*)hi;
    __nv_bfloat162* lp = (__nv_bfloat162*)lo;
    hp[2 * i]     = __nv_bfloat162{h0, h1};
    hp[2 * i + 1] = __nv_bfloat162{h2, h3};
    lp[2 * i]     = __nv_bfloat162{l0, l1};
    lp[2 * i + 1] = __nv_bfloat162{l2, l3};
}

// ---------------------------------------------------------------------------
// helpers
// ---------------------------------------------------------------------------
__device__ __forceinline__ unsigned smem_u32(const void* p)
{
    return (unsigned)__cvta_generic_to_shared(p);
}

__device__ __forceinline__ void ldsm_x4(unsigned addr, unsigned& r0, unsigned& r1,
                                        unsigned& r2, unsigned& r3)
{
    asm volatile("ldmatrix.sync.aligned.m8n8.x4.shared.b16 {%0,%1,%2,%3}, [%4];"
                 : "=r"(r0), "=r"(r1), "=r"(r2), "=r"(r3) : "r"(addr));
}

__device__ __forceinline__ void mma16816(float* d, const unsigned* a,
                                         unsigned b0, unsigned b1)
{
    asm volatile(
        "mma.sync.aligned.m16n8k16.row.col.f32.bf16.bf16.f32 "
        "{%0,%1,%2,%3},{%4,%5,%6,%7},{%8,%9},{%0,%1,%2,%3};"
        : "+f"(d[0]), "+f"(d[1]), "+f"(d[2]), "+f"(d[3])
        : "r"(a[0]), "r"(a[1]), "r"(a[2]), "r"(a[3]), "r"(b0), "r"(b1));
}

#define CP_ASYNC16(dst_u32, src_ptr) \
    asm volatile("cp.async.ca.shared.global [%0], [%1], 16;" \
                 :: "r"(dst_u32), "l"(src_ptr))
#define CP_COMMIT() asm volatile("cp.async.commit_group;")
#define CP_WAIT(N)  asm volatile("cp.async.wait_group %0;" :: "n"(N))

// ---------------------------------------------------------------------------
// Tensor-core precompute GEMM (HMMA, proven since R6):
//   P = Xhi@Whi^T + Xhi@Wlo^T + Xlo@Whi^T + (bi + bh)
// ---------------------------------------------------------------------------
__global__ __launch_bounds__(256) void gemm_pre_bf16(
    const float* __restrict__ bi, const float* __restrict__ bh)
{
    __shared__ uint4 sA[2][128 * 5];
    __shared__ uint4 sB[2][128 * 5];
    __shared__ float sBias[128];

    const int m0 = blockIdx.y * 128;
    const int n0 = blockIdx.x * 128;
    const int tid = threadIdx.x;
    const int wid = tid >> 5;
    const int lane = tid & 31;
    const int warp_m = wid >> 1;
    const int warp_n = wid & 1;

    if (tid < 128) sBias[tid] = bi[n0 + tid] + bh[n0 + tid];

    const __nv_bfloat16* Aseg[3] = { g_Xhi, g_Xhi, g_Xlo };
    const __nv_bfloat16* Bseg[3] = { g_Whi, g_Wlo, g_Whi };

    const int r0u = tid >> 2;
    const int c0u = tid & 3;
    const size_t aOff0 = (size_t)(m0 + r0u) * H_ + c0u * 8;
    const size_t aOff1 = aOff0 + (size_t)64 * H_;
    const size_t bOff0 = (size_t)(n0 + r0u) * H_ + c0u * 8;
    const size_t bOff1 = bOff0 + (size_t)64 * H_;

    float acc0[8][4], acc1[8][4];
    #pragma unroll
    for (int j = 0; j < 8; j++)
        #pragma unroll
        for (int q = 0; q < 4; q++) { acc0[j][q] = 0.f; acc1[j][q] = 0.f; }

    uint4 pa0 = *(const uint4*)(Aseg[0] + aOff0);
    uint4 pa1 = *(const uint4*)(Aseg[0] + aOff1);
    uint4 pb0 = *(const uint4*)(Bseg[0] + bOff0);
    uint4 pb1 = *(const uint4*)(Bseg[0] + bOff1);

    #pragma unroll 1
    for (int ci = 0; ci < 96; ci++) {
        uint4* bufA = sA[ci & 1];
        uint4* bufB = sB[ci & 1];
        bufA[r0u * 5 + c0u] = pa0;
        bufA[(r0u + 64) * 5 + c0u] = pa1;
        bufB[r0u * 5 + c0u] = pb0;
        bufB[(r0u + 64) * 5 + c0u] = pb1;
        __syncthreads();

        if (ci < 95) {
            const int cn = ci + 1;
            const int sg = cn >> 5;
            const size_t k2 = (size_t)(cn & 31) * 32;
            pa0 = *(const uint4*)(Aseg[sg] + aOff0 + k2);
            pa1 = *(const uint4*)(Aseg[sg] + aOff1 + k2);
            pb0 = *(const uint4*)(Bseg[sg] + bOff0 + k2);
            pb1 = *(const uint4*)(Bseg[sg] + bOff1 + k2);
        }

        const unsigned saA = smem_u32(bufA);
        const unsigned saB = smem_u32(bufB);

        #pragma unroll
        for (int ks = 0; ks < 2; ks++) {
            unsigned a0[4], a1[4];
            {
                const int row = warp_m * 32 + (lane & 7) + ((lane >> 3) & 1) * 8;
                const int cu = ks * 2 + (lane >> 4);
                ldsm_x4(saA + (unsigned)((row * 5 + cu) * 16),
                        a0[0], a0[1], a0[2], a0[3]);
                ldsm_x4(saA + (unsigned)(((row + 16) * 5 + cu) * 16),
                        a1[0], a1[1], a1[2], a1[3]);
            }
            unsigned b[4][4];
            {
                const int rb = warp_n * 64 + (lane & 7) + ((lane >> 4) & 1) * 8;
                const int cu = ks * 2 + ((lane >> 3) & 1);
                #pragma unroll
                for (int g = 0; g < 4; g++)
                    ldsm_x4(saB + (unsigned)(((rb + g * 16) * 5 + cu) * 16),
                            b[g][0], b[g][1], b[g][2], b[g][3]);
            }
            #pragma unroll
            for (int g = 0; g < 4; g++) {
                mma16816(acc0[2 * g],     a0, b[g][0], b[g][1]);
                mma16816(acc0[2 * g + 1], a0, b[g][2], b[g][3]);
                mma16816(acc1[2 * g],     a1, b[g][0], b[g][1]);
                mma16816(acc1[2 * g + 1], a1, b[g][2], b[g][3]);
            }
        }
        __syncthreads();
    }

    const int mrow = m0 + warp_m * 32 + (lane >> 2);
    const int ncol0 = warp_n * 64 + 2 * (lane & 3);
    #pragma unroll
    for (int i = 0; i < 2; i++) {
        const int r = mrow + i * 16;
        #pragma unroll
        for (int j = 0; j < 8; j++) {
            const int cc = ncol0 + j * 8;
            const float b0 = sBias[cc];
            const float b1 = sBias[cc + 1];
            const float* av = (i == 0) ? acc0[j] : acc1[j];
            float2 v0 = make_float2(av[0] + b0, av[1] + b1);
            float2 v1 = make_float2(av[2] + b0, av[3] + b1);
            *(float2*)&g_P[(size_t)r * H_ + n0 + cc] = v0;
            *(float2*)&g_P[(size_t)(r + 8) * H_ + n0 + cc] = v1;
        }
    }
}

// ---------------------------------------------------------------------------
// Kernel 2: persistent TENSOR-CORE recurrence, v7: batch-group partitioning.
// Batch rows are INDEPENDENT chains, so the grid is split into 4 decoupled
// groups: group g (= bid & 3) owns b-rows [32g, 32g+32) and runs its own
// 32-block barrier (verbatim R9 atomic mechanism, count 32). Block
// (ntile = bid>>2) covers n-cols [32*ntile, +32) x its group's 32 b-rows.
// 8 warps = 2 bg (16 b-rows) x 2 kh (512 k) x 2 ng (16 n-cols).
// Math identical to R9: out = h_hi@Whi^T + h_hi@Wlo^T + h_lo@Whi^T,
// 6 accumulator chains, SMEM k-half reduction, all stores before the barrier.
// h staged per-warp via cp.async, 4-deep pipeline, BK=32 (16 chunks).
// SMEM: W [split][u128][n32] = 128K + staging 8w x 4buf x 2560B = 80K
//       + reduce 4K = 217088 B.
// ---------------------------------------------------------------------------
#define SW3_BYTES  131072
#define SW3_SPLIT  65536
#define SH3_CH     1280                          // per-split per-chunk (16*5*16)
#define SH3_BUF    2560                          // chunk buf (hi+lo)
#define SH3_WARP   (4 * SH3_BUF)                 // 10240
#define RED3_OFF   (SW3_BYTES + 8 * SH3_WARP)    // 212992
#define RNN7_SMEM  (RED3_OFF + 4096)             // 217088

__global__ __launch_bounds__(NTHR, 1) void rnn_seq_mma7(
    const float* __restrict__ hx, const float* __restrict__ Wh,
    float* __restrict__ outx, float* __restrict__ hn)
{
    extern __shared__ char sm[];
    char* sW = sm;                    // [split][u(128)][n(32)] 16B units
    char* sH = sm + SW3_BYTES;        // 8 x per-warp regions (4 bufs each)
    float* sred = (float*)(sm + RED3_OFF);

    const int tid = threadIdx.x;
    const int bid = blockIdx.x;
    const int warp = tid >> 5;
    const int lane = tid & 31;

    const int grp   = bid & 3;           // batch group (32 b-rows)
    const int n0    = (bid >> 2) * 32;   // block n base
    const int brow0 = grp * 32;          // block b base
    const int bg  = warp >> 2;           // 0..1: 16-row b-group
    const int kh  = (warp >> 1) & 1;     // k-half (512 each)
    const int ng  = warp & 1;            // n-half (16 cols each)
    const int r0w = brow0 + 16 * bg;

    // --- load + split Whh rows n0..n0+31 into SMEM (once per layer) ---
    #pragma unroll
    for (int j = 0; j < 16; j++) {
        int g = tid + 256 * j;        // 0..4095
        int n = g & 31;
        int u = g >> 5;               // 0..127
        const float* src = Wh + (size_t)(n0 + n) * H_ + u * 8;
        float4 f0 = *(const float4*)src;
        float4 f1 = *(const float4*)(src + 4);
        float fv[8] = { f0.x, f0.y, f0.z, f0.w, f1.x, f1.y, f1.z, f1.w };
        union { __nv_bfloat162 b2[4]; uint4 u4; } hi_, lo_;
        #pragma unroll
        for (int q = 0; q < 4; q++) {
            __nv_bfloat16 h0 = __float2bfloat16_rn(fv[2 * q]);
            __nv_bfloat16 h1 = __float2bfloat16_rn(fv[2 * q + 1]);
            hi_.b2[q] = __nv_bfloat162{h0, h1};
            lo_.b2[q] = __nv_bfloat162{
                __float2bfloat16_rn(fv[2 * q] - __bfloat162float(h0)),
                __float2bfloat16_rn(fv[2 * q + 1] - __bfloat162float(h1))};
        }
        int off = (u * 32 + n) * 16;
        *(uint4*)(sW + off) = hi_.u4;
        *(uint4*)(sW + SW3_SPLIT + off) = lo_.u4;
    }

    // --- init h: g_hb[0] = split(hx) ---
    {
        int gi = bid * NTHR + tid;
        float4 v = ((const float4*)hx)[gi];
        union { __nv_bfloat162 b2[2]; uint2 u; } hi_, lo_;
        __nv_bfloat16 h0 = __float2bfloat16_rn(v.x);
        __nv_bfloat16 h1 = __float2bfloat16_rn(v.y);
        __nv_bfloat16 h2 = __float2bfloat16_rn(v.z);
        __nv_bfloat16 h3 = __float2bfloat16_rn(v.w);
        hi_.b2[0] = __nv_bfloat162{h0, h1};
        hi_.b2[1] = __nv_bfloat162{h2, h3};
        lo_.b2[0] = __nv_bfloat162{
            __float2bfloat16_rn(v.x - __bfloat162float(h0)),
            __float2bfloat16_rn(v.y - __bfloat162float(h1))};
        lo_.b2[1] = __nv_bfloat162{
            __float2bfloat16_rn(v.z - __bfloat162float(h2)),
            __float2bfloat16_rn(v.w - __bfloat162float(h3))};
        ((uint2*)g_hb[0][0])[gi] = hi_.u;
        ((uint2*)g_hb[0][1])[gi] = lo_.u;
    }
    grid_barrier_full();   // init is scattered across all blocks

    // per-thread constants
    const unsigned swu = smem_u32(sW);
    const unsigned shw = smem_u32(sH) + warp * SH3_WARP;
    const int srow = lane & 15;                  // staging row 0..15
    const int su0  = (lane >> 4) * 2;            // staging unit base 0/2
    const unsigned st_off = (unsigned)((srow * 5 + su0) * 16);
    const int arow = (lane & 7) + ((lane >> 3) & 1) * 8;
    const unsigned bn0 = (unsigned)(16 * ng + (lane & 7));
    const unsigned bn1 = bn0 + 8;
    const int mr0 = r0w + (lane >> 2);
    const int mr1 = mr0 + 8;
    const int cc0 = n0 + 16 * ng + 2 * (lane & 3);   // tile 0; tile 1 = +8

    for (int t = 0; t < T_; t++) {
        const __nv_bfloat16* __restrict__ hhi = g_hb[t & 1][0];
        const __nv_bfloat16* __restrict__ hlo = g_hb[t & 1][1];
        __nv_bfloat16* __restrict__ nhi = g_hb[(t + 1) & 1][0];
        __nv_bfloat16* __restrict__ nlo = g_hb[(t + 1) & 1][1];
        const float* __restrict__ Pt = g_P + (size_t)t * B_ * H_;
        float* __restrict__ ox = outx + (size_t)t * B_ * H_;

        float2 Pv00, Pv01, Pv10, Pv11;
        if (kh == 0) {
            Pv00 = *(const float2*)&Pt[(size_t)mr0 * H_ + cc0];
            Pv01 = *(const float2*)&Pt[(size_t)mr0 * H_ + cc0 + 8];
            Pv10 = *(const float2*)&Pt[(size_t)mr1 * H_ + cc0];
            Pv11 = *(const float2*)&Pt[(size_t)mr1 * H_ + cc0 + 8];
        }

        float aA0[4] = {0,0,0,0}, aB0[4] = {0,0,0,0}, aC0[4] = {0,0,0,0};
        float aA1[4] = {0,0,0,0}, aB1[4] = {0,0,0,0}, aC1[4] = {0,0,0,0};

        // global staging source (this lane): row r0w+srow, k-half kh
        const __nv_bfloat16* ghi =
            hhi + (size_t)(r0w + srow) * H_ + kh * 512 + su0 * 8;
        const __nv_bfloat16* glo =
            hlo + (size_t)(r0w + srow) * H_ + kh * 512 + su0 * 8;

        // prologue: issue chunks 0..2
        #pragma unroll
        for (int pc = 0; pc < 3; pc++) {
            unsigned d = shw + pc * SH3_BUF + st_off;
            const __nv_bfloat16* s_hi = ghi + pc * 32;
            const __nv_bfloat16* s_lo = glo + pc * 32;
            #pragma unroll
            for (int i = 0; i < 2; i++) {
                CP_ASYNC16(d + i * 16, (const char*)(s_hi + i * 8));
                CP_ASYNC16(d + SH3_CH + i * 16, (const char*)(s_lo + i * 8));
            }
            CP_COMMIT();
        }

        #pragma unroll 1
        for (int kc = 0; kc < 16; kc++) {
            if (kc + 3 < 16) {
                unsigned d = shw + ((kc + 3) & 3) * SH3_BUF + st_off;
                const __nv_bfloat16* s_hi = ghi + (kc + 3) * 32;
                const __nv_bfloat16* s_lo = glo + (kc + 3) * 32;
                #pragma unroll
                for (int i = 0; i < 2; i++) {
                    CP_ASYNC16(d + i * 16, (const char*)(s_hi + i * 8));
                    CP_ASYNC16(d + SH3_CH + i * 16, (const char*)(s_lo + i * 8));
                }
                CP_COMMIT();
            }
            if (kc <= 12)      { CP_WAIT(3); }
            else if (kc == 13) { CP_WAIT(2); }
            else if (kc == 14) { CP_WAIT(1); }
            else               { CP_WAIT(0); }
            __syncwarp();

            const unsigned ab = shw + (kc & 3) * SH3_BUF;
            // B fragments: whole chunk (4 units = 2 k-steps) per n8-tile
            const unsigned ua = (unsigned)(kh * 64 + kc * 4 + (lane >> 3));
            unsigned ba0 = swu + (ua * 32 + bn0) * 16;
            unsigned ba1 = swu + (ua * 32 + bn1) * 16;
            unsigned bh0[4], bl0[4], bh1[4], bl1[4];
            ldsm_x4(ba0, bh0[0], bh0[1], bh0[2], bh0[3]);
            ldsm_x4(ba0 + SW3_SPLIT, bl0[0], bl0[1], bl0[2], bl0[3]);
            ldsm_x4(ba1, bh1[0], bh1[1], bh1[2], bh1[3]);
            ldsm_x4(ba1 + SW3_SPLIT, bl1[0], bl1[1], bl1[2], bl1[3]);
            #pragma unroll
            for (int q = 0; q < 2; q++) {
                unsigned ahi[4], alo[4];
                const unsigned cu = (unsigned)(q * 2 + (lane >> 4));
                const unsigned aaddr = ab + (unsigned)((arow * 5 + cu) * 16);
                ldsm_x4(aaddr, ahi[0], ahi[1], ahi[2], ahi[3]);
                ldsm_x4(aaddr + SH3_CH, alo[0], alo[1], alo[2], alo[3]);
                mma16816(aA0, ahi, bh0[2 * q], bh0[2 * q + 1]);
                mma16816(aB0, ahi, bl0[2 * q], bl0[2 * q + 1]);
                mma16816(aC0, alo, bh0[2 * q], bh0[2 * q + 1]);
                mma16816(aA1, ahi, bh1[2 * q], bh1[2 * q + 1]);
                mma16816(aB1, ahi, bl1[2 * q], bl1[2 * q + 1]);
                mma16816(aC1, alo, bh1[2 * q], bh1[2 * q + 1]);
            }
        }

        // combine 3 chains, then reduce the 2 k-halves through SMEM
        float s0[4], s1[4];
        #pragma unroll
        for (int i = 0; i < 4; i++) {
            s0[i] = (aA0[i] + aB0[i]) + aC0[i];
            s1[i] = (aA1[i] + aB1[i]) + aC1[i];
        }
        if (kh == 1) {
            float4* dst = (float4*)&sred[((bg * 2 + ng) * 32 + lane) * 8];
            dst[0] = make_float4(s0[0], s0[1], s0[2], s0[3]);
            dst[1] = make_float4(s1[0], s1[1], s1[2], s1[3]);
        }
        __syncthreads();
        if (kh == 0) {
            const float4* srd =
                (const float4*)&sred[((bg * 2 + ng) * 32 + lane) * 8];
            float4 r0 = srd[0], r1 = srd[1];
            s0[0] += r0.x; s0[1] += r0.y; s0[2] += r0.z; s0[3] += r0.w;
            s1[0] += r1.x; s1[1] += r1.y; s1[2] += r1.z; s1[3] += r1.w;

            float v00 = tanhf(s0[0] + Pv00.x);
            float v01 = tanhf(s0[1] + Pv00.y);
            float v10 = tanhf(s0[2] + Pv10.x);
            float v11 = tanhf(s0[3] + Pv10.y);
            float w00 = tanhf(s1[0] + Pv01.x);
            float w01 = tanhf(s1[1] + Pv01.y);
            float w10 = tanhf(s1[2] + Pv11.x);
            float w11 = tanhf(s1[3] + Pv11.y);

            const size_t i0 = (size_t)mr0 * H_ + cc0;
            const size_t i1 = (size_t)mr1 * H_ + cc0;
            *(float2*)&ox[i0]     = make_float2(v00, v01);
            *(float2*)&ox[i0 + 8] = make_float2(w00, w01);
            *(float2*)&ox[i1]     = make_float2(v10, v11);
            *(float2*)&ox[i1 + 8] = make_float2(w10, w11);

            #pragma unroll
            for (int e = 0; e < 4; e++) {
                float x0 = (e == 0) ? v00 : (e == 1) ? w00 : (e == 2) ? v10 : w10;
                float x1 = (e == 0) ? v01 : (e == 1) ? w01 : (e == 2) ? v11 : w11;
                size_t ix = (e < 2) ? (i0 + (e & 1) * 8) : (i1 + (e & 1) * 8);
                __nv_bfloat16 hh0 = __float2bfloat16_rn(x0);
                __nv_bfloat16 hh1 = __float2bfloat16_rn(x1);
                *(__nv_bfloat162*)&nhi[ix] = __nv_bfloat162{hh0, hh1};
                *(__nv_bfloat162*)&nlo[ix] = __nv_bfloat162{
                    __float2bfloat16_rn(x0 - __bfloat162float(hh0)),
                    __float2bfloat16_rn(x1 - __bfloat162float(hh1))};
            }
            if (t == T_ - 1) {
                *(float2*)&hn[i0]     = make_float2(v00, v01);
                *(float2*)&hn[i0 + 8] = make_float2(w00, w01);
                *(float2*)&hn[i1]     = make_float2(v10, v11);
                *(float2*)&hn[i1 + 8] = make_float2(w10, w11);
            }
        }
        grid_barrier_grp(grp);
    }
}

// ---------------------------------------------------------------------------
// Launch: per layer: split X, split W_ih, HMMA GEMM, recurrence v7.
// 16 graph nodes total.
// ---------------------------------------------------------------------------
extern "C" void kernel_launch(void* const* d_in, const int* in_sizes, int n_in,
                              void* d_out, int out_size)
{
    const float* inputs = (const float*)d_in[0];   // [T,B,H]
    const float* hxs    = (const float*)d_in[1];   // [L,B,H]
    const float* W_ih   = (const float*)d_in[2];   // [L,H,H]
    const float* b_ih   = (const float*)d_in[3];   // [L,H]
    const float* W_hh   = (const float*)d_in[4];   // [L,H,H]
    const float* b_hh   = (const float*)d_in[5];   // [L,H]

    float* out  = (float*)d_out;
    float* outx = out;                               // [T,B,H]
    float* outh = out + (size_t)T_ * B_ * H_;        // [L,B,H]

    static bool attr_done = false;
    if (!attr_done) {
        cudaFuncSetAttribute(rnn_seq_mma7,
                             cudaFuncAttributeMaxDynamicSharedMemorySize,
                             RNN7_SMEM);
        attr_done = true;
    }

    __nv_bfloat16* xhi; cudaGetSymbolAddress((void**)&xhi, g_Xhi);
    __nv_bfloat16* xlo; cudaGetSymbolAddress((void**)&xlo, g_Xlo);
    __nv_bfloat16* whi; cudaGetSymbolAddress((void**)&whi, g_Whi);
    __nv_bfloat16* wlo; cudaGetSymbolAddress((void**)&wlo, g_Wlo);

    const int nX4 = MTOT * H_ / 4;
    const int nW4 = H_ * H_ / 4;

    dim3 pre_grid(H_ / 128, MTOT / 128);             // (8, 256)

    for (int l = 0; l < L_; l++) {
        const float* x_l = (l == 0) ? inputs : outx;
        split_bf16<<<nX4 / 256, 256>>>(x_l, xhi, xlo, nX4);
        split_bf16<<<nW4 / 256, 256>>>(W_ih + (size_t)l * H_ * H_, whi, wlo, nW4);
        gemm_pre_bf16<<<pre_grid, 256>>>(b_ih + (size_t)l * H_,
                                         b_hh + (size_t)l * H_);
        rnn_seq_mma7<<<NBLK, NTHR, RNN7_SMEM>>>(
            hxs + (size_t)l * B_ * H_,
            W_hh + (size_t)l * H_ * H_,
            outx,
            outh + (size_t)l * B_ * H_);
    }
}

// round 17
// speedup vs baseline: 1.4950x; 1.1982x over previous
#include <cuda_runtime.h>
#include <cuda_bf16.h>
#include <math.h>

// Problem constants
#define T_  256
#define B_  128
#define H_  1024
#define L_  4
#define MTOT (T_ * B_)   // 32768

#define NBLK 128
#define NTHR 256

// Scratch
__device__ float g_P[(size_t)MTOT * H_];
__device__ __align__(16) __nv_bfloat16 g_hb[2][2][(size_t)B_ * H_]; // [buf][hi/lo]

// bf16 hi/lo split scratch
__device__ __nv_bfloat16 g_Xhi[(size_t)MTOT * H_];
__device__ __nv_bfloat16 g_Xlo[(size_t)MTOT * H_];
__device__ __nv_bfloat16 g_Whi[(size_t)H_ * H_];
__device__ __nv_bfloat16 g_Wlo[(size_t)H_ * H_];

// barrier state: full-grid (init) + per-half (step), padded to separate lines
__device__ volatile unsigned g_bar_gen = 0;
__device__ unsigned g_bar_cnt = 0;
__device__ volatile unsigned g_hgen[2 * 32];   // [half*32]
__device__ unsigned g_hcnt[2 * 32];

__device__ __forceinline__ void grid_barrier_full()
{
    __syncthreads();
    if (threadIdx.x == 0) {
        unsigned gen = g_bar_gen;
        __threadfence();
        if (atomicAdd(&g_bar_cnt, 1) == NBLK - 1) {
            atomicExch(&g_bar_cnt, 0);
            __threadfence();
            g_bar_gen = gen + 1;
        } else {
            while (g_bar_gen == gen) { }
            __threadfence();
        }
    }
    __syncthreads();
}

// per-half barrier over 64 blocks (mechanism identical to the proven one;
// correctness of half scope: block (n0, half) reads h rows only from its own
// b-half, which is written only by blocks of the same half — proven in R10)
__device__ __forceinline__ void half_barrier(int half)
{
    __syncthreads();
    if (threadIdx.x == 0) {
        const int idx = half * 32;
        unsigned gen = g_hgen[idx];
        __threadfence();
        if (atomicAdd(&g_hcnt[idx], 1) == NBLK / 2 - 1) {
            atomicExch(&g_hcnt[idx], 0);
            __threadfence();
            g_hgen[idx] = gen + 1;
        } else {
            while (g_hgen[idx] == gen) { }
            __threadfence();
        }
    }
    __syncthreads();
}

// ---------------------------------------------------------------------------
// fp32 -> (hi, lo) bf16 split.
// ---------------------------------------------------------------------------
__global__ __launch_bounds__(256) void split_bf16(
    const float* __restrict__ src,
    __nv_bfloat16* __restrict__ hi, __nv_bfloat16* __restrict__ lo, int n4)
{
    int i = blockIdx.x * 256 + threadIdx.x;
    if (i >= n4) return;
    float4 v = ((const float4*)src)[i];
    __nv_bfloat16 h0 = __float2bfloat16_rn(v.x);
    __nv_bfloat16 h1 = __float2bfloat16_rn(v.y);
    __nv_bfloat16 h2 = __float2bfloat16_rn(v.z);
    __nv_bfloat16 h3 = __float2bfloat16_rn(v.w);
    __nv_bfloat16 l0 = __float2bfloat16_rn(v.x - __bfloat162float(h0));
    __nv_bfloat16 l1 = __float2bfloat16_rn(v.y - __bfloat162float(h1));
    __nv_bfloat16 l2 = __float2bfloat16_rn(v.z - __bfloat162float(h2));
    __nv_bfloat16 l3 = __float2bfloat16_rn(v.w - __bfloat162float(h3));
    __nv_bfloat162* hp = (__nv_bfloat162*)hi;
    __nv_bfloat162* lp = (__nv_bfloat162*)lo;
    hp[2 * i]     = __nv_bfloat162{h0, h1};
    hp[2 * i + 1] = __nv_bfloat162{h2, h3};
    lp[2 * i]     = __nv_bfloat162{l0, l1};
    lp[2 * i + 1] = __nv_bfloat162{l2, l3};
}

// ---------------------------------------------------------------------------
// helpers
// ---------------------------------------------------------------------------
__device__ __forceinline__ unsigned smem_u32(const void* p)
{
    return (unsigned)__cvta_generic_to_shared(p);
}

__device__ __forceinline__ void ldsm_x4(unsigned addr, unsigned& r0, unsigned& r1,
                                        unsigned& r2, unsigned& r3)
{
    asm volatile("ldmatrix.sync.aligned.m8n8.x4.shared.b16 {%0,%1,%2,%3}, [%4];"
                 : "=r"(r0), "=r"(r1), "=r"(r2), "=r"(r3) : "r"(addr));
}

__device__ __forceinline__ void mma16816(float* d, const unsigned* a,
                                         unsigned b0, unsigned b1)
{
    asm volatile(
        "mma.sync.aligned.m16n8k16.row.col.f32.bf16.bf16.f32 "
        "{%0,%1,%2,%3},{%4,%5,%6,%7},{%8,%9},{%0,%1,%2,%3};"
        : "+f"(d[0]), "+f"(d[1]), "+f"(d[2]), "+f"(d[3])
        : "r"(a[0]), "r"(a[1]), "r"(a[2]), "r"(a[3]), "r"(b0), "r"(b1));
}

#define CP_ASYNC16(dst_u32, src_ptr) \
    asm volatile("cp.async.ca.shared.global [%0], [%1], 16;" \
                 :: "r"(dst_u32), "l"(src_ptr))
#define CP_COMMIT() asm volatile("cp.async.commit_group;")
#define CP_WAIT(N)  asm volatile("cp.async.wait_group %0;" :: "n"(N))

// ---------------------------------------------------------------------------
// Tensor-core precompute GEMM (HMMA, proven since R6):
//   P = Xhi@Whi^T + Xhi@Wlo^T + Xlo@Whi^T + (bi + bh)
// ---------------------------------------------------------------------------
__global__ __launch_bounds__(256) void gemm_pre_bf16(
    const float* __restrict__ bi, const float* __restrict__ bh)
{
    __shared__ uint4 sA[2][128 * 5];
    __shared__ uint4 sB[2][128 * 5];
    __shared__ float sBias[128];

    const int m0 = blockIdx.y * 128;
    const int n0 = blockIdx.x * 128;
    const int tid = threadIdx.x;
    const int wid = tid >> 5;
    const int lane = tid & 31;
    const int warp_m = wid >> 1;
    const int warp_n = wid & 1;

    if (tid < 128) sBias[tid] = bi[n0 + tid] + bh[n0 + tid];

    const __nv_bfloat16* Aseg[3] = { g_Xhi, g_Xhi, g_Xlo };
    const __nv_bfloat16* Bseg[3] = { g_Whi, g_Wlo, g_Whi };

    const int r0u = tid >> 2;
    const int c0u = tid & 3;
    const size_t aOff0 = (size_t)(m0 + r0u) * H_ + c0u * 8;
    const size_t aOff1 = aOff0 + (size_t)64 * H_;
    const size_t bOff0 = (size_t)(n0 + r0u) * H_ + c0u * 8;
    const size_t bOff1 = bOff0 + (size_t)64 * H_;

    float acc0[8][4], acc1[8][4];
    #pragma unroll
    for (int j = 0; j < 8; j++)
        #pragma unroll
        for (int q = 0; q < 4; q++) { acc0[j][q] = 0.f; acc1[j][q] = 0.f; }

    uint4 pa0 = *(const uint4*)(Aseg[0] + aOff0);
    uint4 pa1 = *(const uint4*)(Aseg[0] + aOff1);
    uint4 pb0 = *(const uint4*)(Bseg[0] + bOff0);
    uint4 pb1 = *(const uint4*)(Bseg[0] + bOff1);

    #pragma unroll 1
    for (int ci = 0; ci < 96; ci++) {
        uint4* bufA = sA[ci & 1];
        uint4* bufB = sB[ci & 1];
        bufA[r0u * 5 + c0u] = pa0;
        bufA[(r0u + 64) * 5 + c0u] = pa1;
        bufB[r0u * 5 + c0u] = pb0;
        bufB[(r0u + 64) * 5 + c0u] = pb1;
        __syncthreads();

        if (ci < 95) {
            const int cn = ci + 1;
            const int sg = cn >> 5;
            const size_t k2 = (size_t)(cn & 31) * 32;
            pa0 = *(const uint4*)(Aseg[sg] + aOff0 + k2);
            pa1 = *(const uint4*)(Aseg[sg] + aOff1 + k2);
            pb0 = *(const uint4*)(Bseg[sg] + bOff0 + k2);
            pb1 = *(const uint4*)(Bseg[sg] + bOff1 + k2);
        }

        const unsigned saA = smem_u32(bufA);
        const unsigned saB = smem_u32(bufB);

        #pragma unroll
        for (int ks = 0; ks < 2; ks++) {
            unsigned a0[4], a1[4];
            {
                const int row = warp_m * 32 + (lane & 7) + ((lane >> 3) & 1) * 8;
                const int cu = ks * 2 + (lane >> 4);
                ldsm_x4(saA + (unsigned)((row * 5 + cu) * 16),
                        a0[0], a0[1], a0[2], a0[3]);
                ldsm_x4(saA + (unsigned)(((row + 16) * 5 + cu) * 16),
                        a1[0], a1[1], a1[2], a1[3]);
            }
            unsigned b[4][4];
            {
                const int rb = warp_n * 64 + (lane & 7) + ((lane >> 4) & 1) * 8;
                const int cu = ks * 2 + ((lane >> 3) & 1);
                #pragma unroll
                for (int g = 0; g < 4; g++)
                    ldsm_x4(saB + (unsigned)(((rb + g * 16) * 5 + cu) * 16),
                            b[g][0], b[g][1], b[g][2], b[g][3]);
            }
            #pragma unroll
            for (int g = 0; g < 4; g++) {
                mma16816(acc0[2 * g],     a0, b[g][0], b[g][1]);
                mma16816(acc0[2 * g + 1], a0, b[g][2], b[g][3]);
                mma16816(acc1[2 * g],     a1, b[g][0], b[g][1]);
                mma16816(acc1[2 * g + 1], a1, b[g][2], b[g][3]);
            }
        }
        __syncthreads();
    }

    const int mrow = m0 + warp_m * 32 + (lane >> 2);
    const int ncol0 = warp_n * 64 + 2 * (lane & 3);
    #pragma unroll
    for (int i = 0; i < 2; i++) {
        const int r = mrow + i * 16;
        #pragma unroll
        for (int j = 0; j < 8; j++) {
            const int cc = ncol0 + j * 8;
            const float b0 = sBias[cc];
            const float b1 = sBias[cc + 1];
            const float* av = (i == 0) ? acc0[j] : acc1[j];
            float2 v0 = make_float2(av[0] + b0, av[1] + b1);
            float2 v1 = make_float2(av[2] + b0, av[3] + b1);
            *(float2*)&g_P[(size_t)r * H_ + n0 + cc] = v0;
            *(float2*)&g_P[(size_t)(r + 8) * H_ + n0 + cc] = v1;
        }
    }
}

// ---------------------------------------------------------------------------
// Kernel 2: persistent TENSOR-CORE recurrence — R9 compute loop VERBATIM
// (proven 15.47 ms), with two R10-proven sync reductions:
//   (a) per-step barrier scoped to the 64 blocks of this b-half
//   (b) barrier skipped on the last step.
// 128 blocks x 256 threads; block tile 64 b-rows x 16 n-cols; 8 warps =
// 4 b-groups x 2 k-halves; 6 accumulator chains; SMEM k-reduction; 4-deep
// cp.async pipeline; ALL stores before the barrier.
// SMEM: W 64 KB + staging 8w x 4buf x 4608 B = 144 KB + reduce 4 KB = 217 KB.
// ---------------------------------------------------------------------------
#define SW_BYTES2  65536
#define SW_SPLIT2  32768
#define SHW_CH     2304
#define SHW_BUFB   4608
#define SHW_WARP   (4 * SHW_BUFB)               // 18432
#define RED_OFF    (SW_BYTES2 + 8 * SHW_WARP)   // 212992
#define RNN3_SMEM  (RED_OFF + 4096)             // 217088

__global__ __launch_bounds__(NTHR, 1) void rnn_seq_mma3(
    const float* __restrict__ hx, const float* __restrict__ Wh,
    float* __restrict__ outx, float* __restrict__ hn)
{
    extern __shared__ char sm[];
    char* sW = sm;
    char* sH = sm + SW_BYTES2;
    float* sred = (float*)(sm + RED_OFF);

    const int tid = threadIdx.x;
    const int bid = blockIdx.x;
    const int warp = tid >> 5;
    const int lane = tid & 31;

    const int n0   = (bid >> 1) * 16;
    const int half = bid & 1;
    const int b0   = half * 64;
    const int bg  = warp >> 1;
    const int kh  = warp & 1;
    const int r0w = b0 + 16 * bg;

    #pragma unroll
    for (int j = 0; j < 8; j++) {
        int g = tid + 256 * j;
        int n = g & 15;
        int u = g >> 4;
        const float* src = Wh + (size_t)(n0 + n) * H_ + u * 8;
        float4 f0 = *(const float4*)src;
        float4 f1 = *(const float4*)(src + 4);
        float fv[8] = { f0.x, f0.y, f0.z, f0.w, f1.x, f1.y, f1.z, f1.w };
        union { __nv_bfloat162 b2[4]; uint4 u4; } hi_, lo_;
        #pragma unroll
        for (int q = 0; q < 4; q++) {
            __nv_bfloat16 h0 = __float2bfloat16_rn(fv[2 * q]);
            __nv_bfloat16 h1 = __float2bfloat16_rn(fv[2 * q + 1]);
            hi_.b2[q] = __nv_bfloat162{h0, h1};
            lo_.b2[q] = __nv_bfloat162{
                __float2bfloat16_rn(fv[2 * q] - __bfloat162float(h0)),
                __float2bfloat16_rn(fv[2 * q + 1] - __bfloat162float(h1))};
        }
        int off = (u * 16 + n) * 16;
        *(uint4*)(sW + off) = hi_.u4;
        *(uint4*)(sW + SW_SPLIT2 + off) = lo_.u4;
    }

    {
        int gi = bid * NTHR + tid;
        float4 v = ((const float4*)hx)[gi];
        union { __nv_bfloat162 b2[2]; uint2 u; } hi_, lo_;
        __nv_bfloat16 h0 = __float2bfloat16_rn(v.x);
        __nv_bfloat16 h1 = __float2bfloat16_rn(v.y);
        __nv_bfloat16 h2 = __float2bfloat16_rn(v.z);
        __nv_bfloat16 h3 = __float2bfloat16_rn(v.w);
        hi_.b2[0] = __nv_bfloat162{h0, h1};
        hi_.b2[1] = __nv_bfloat162{h2, h3};
        lo_.b2[0] = __nv_bfloat162{
            __float2bfloat16_rn(v.x - __bfloat162float(h0)),
            __float2bfloat16_rn(v.y - __bfloat162float(h1))};
        lo_.b2[1] = __nv_bfloat162{
            __float2bfloat16_rn(v.z - __bfloat162float(h2)),
            __float2bfloat16_rn(v.w - __bfloat162float(h3))};
        ((uint2*)g_hb[0][0])[gi] = hi_.u;
        ((uint2*)g_hb[0][1])[gi] = lo_.u;
    }
    grid_barrier_full();

    const unsigned swu = smem_u32(sW);
    const unsigned shw = smem_u32(sH) + warp * SHW_WARP;
    const int srow = lane >> 1;
    const int su0  = (lane & 1) * 4;
    const unsigned st_off = (unsigned)((srow * 9 + su0) * 16);
    const int arow = (lane & 7) + ((lane >> 3) & 1) * 8;
    const unsigned bn0 = (unsigned)(lane & 7);
    const unsigned bn1 = bn0 + 8;
    const int mr0 = r0w + (lane >> 2);
    const int mr1 = mr0 + 8;
    const int cc0 = n0 + 2 * (lane & 3);

    for (int t = 0; t < T_; t++) {
        const __nv_bfloat16* __restrict__ hhi = g_hb[t & 1][0];
        const __nv_bfloat16* __restrict__ hlo = g_hb[t & 1][1];
        __nv_bfloat16* __restrict__ nhi = g_hb[(t + 1) & 1][0];
        __nv_bfloat16* __restrict__ nlo = g_hb[(t + 1) & 1][1];
        const float* __restrict__ Pt = g_P + (size_t)t * B_ * H_;
        float* __restrict__ ox = outx + (size_t)t * B_ * H_;

        float2 Pv00, Pv01, Pv10, Pv11;
        if (kh == 0) {
            Pv00 = *(const float2*)&Pt[(size_t)mr0 * H_ + cc0];
            Pv01 = *(const float2*)&Pt[(size_t)mr0 * H_ + cc0 + 8];
            Pv10 = *(const float2*)&Pt[(size_t)mr1 * H_ + cc0];
            Pv11 = *(const float2*)&Pt[(size_t)mr1 * H_ + cc0 + 8];
        }

        float aA0[4] = {0,0,0,0}, aB0[4] = {0,0,0,0}, aC0[4] = {0,0,0,0};
        float aA1[4] = {0,0,0,0}, aB1[4] = {0,0,0,0}, aC1[4] = {0,0,0,0};

        const __nv_bfloat16* ghi =
            hhi + (size_t)(r0w + srow) * H_ + kh * 512 + su0 * 8;
        const __nv_bfloat16* glo =
            hlo + (size_t)(r0w + srow) * H_ + kh * 512 + su0 * 8;

        #pragma unroll
        for (int pc = 0; pc < 3; pc++) {
            unsigned d = shw + pc * SHW_BUFB + st_off;
            const __nv_bfloat16* s_hi = ghi + pc * 64;
            const __nv_bfloat16* s_lo = glo + pc * 64;
            #pragma unroll
            for (int i = 0; i < 4; i++) {
                CP_ASYNC16(d + i * 16, (const char*)(s_hi + i * 8));
                CP_ASYNC16(d + SHW_CH + i * 16, (const char*)(s_lo + i * 8));
            }
            CP_COMMIT();
        }

        #pragma unroll 1
        for (int kc = 0; kc < 8; kc++) {
            if (kc + 3 < 8) {
                unsigned d = shw + ((kc + 3) & 3) * SHW_BUFB + st_off;
                const __nv_bfloat16* s_hi = ghi + (kc + 3) * 64;
                const __nv_bfloat16* s_lo = glo + (kc + 3) * 64;
                #pragma unroll
                for (int i = 0; i < 4; i++) {
                    CP_ASYNC16(d + i * 16, (const char*)(s_hi + i * 8));
                    CP_ASYNC16(d + SHW_CH + i * 16, (const char*)(s_lo + i * 8));
                }
                CP_COMMIT();
            }
            if (kc <= 4)      { CP_WAIT(3); }
            else if (kc == 5) { CP_WAIT(2); }
            else if (kc == 6) { CP_WAIT(1); }
            else              { CP_WAIT(0); }
            __syncwarp();

            const unsigned ab = shw + (kc & 3) * SHW_BUFB;
            #pragma unroll
            for (int p = 0; p < 2; p++) {
                unsigned ua = (unsigned)(kh * 64 + kc * 8 + p * 4 + (lane >> 3));
                unsigned ba0 = swu + (ua * 16 + bn0) * 16;
                unsigned ba1 = swu + (ua * 16 + bn1) * 16;
                unsigned bh0[4], bl0[4], bh1[4], bl1[4];
                ldsm_x4(ba0, bh0[0], bh0[1], bh0[2], bh0[3]);
                ldsm_x4(ba0 + SW_SPLIT2, bl0[0], bl0[1], bl0[2], bl0[3]);
                ldsm_x4(ba1, bh1[0], bh1[1], bh1[2], bh1[3]);
                ldsm_x4(ba1 + SW_SPLIT2, bl1[0], bl1[1], bl1[2], bl1[3]);
                #pragma unroll
                for (int q = 0; q < 2; q++) {
                    unsigned ahi[4], alo[4];
                    const unsigned cu = (unsigned)(p * 4 + q * 2 + (lane >> 4));
                    const unsigned aaddr = ab + (unsigned)((arow * 9 + cu) * 16);
                    ldsm_x4(aaddr, ahi[0], ahi[1], ahi[2], ahi[3]);
                    ldsm_x4(aaddr + SHW_CH, alo[0], alo[1], alo[2], alo[3]);
                    mma16816(aA0, ahi, bh0[2 * q], bh0[2 * q + 1]);
                    mma16816(aB0, ahi, bl0[2 * q], bl0[2 * q + 1]);
                    mma16816(aC0, alo, bh0[2 * q], bh0[2 * q + 1]);
                    mma16816(aA1, ahi, bh1[2 * q], bh1[2 * q + 1]);
                    mma16816(aB1, ahi, bl1[2 * q], bl1[2 * q + 1]);
                    mma16816(aC1, alo, bh1[2 * q], bh1[2 * q + 1]);
                }
            }
        }

        float s0[4], s1[4];
        #pragma unroll
        for (int i = 0; i < 4; i++) {
            s0[i] = (aA0[i] + aB0[i]) + aC0[i];
            s1[i] = (aA1[i] + aB1[i]) + aC1[i];
        }
        if (kh == 1) {
            float4* dst = (float4*)&sred[(bg * 32 + lane) * 8];
            dst[0] = make_float4(s0[0], s0[1], s0[2], s0[3]);
            dst[1] = make_float4(s1[0], s1[1], s1[2], s1[3]);
        }
        __syncthreads();
        if (kh == 0) {
            const float4* srd = (const float4*)&sred[(bg * 32 + lane) * 8];
            float4 r0 = srd[0], r1 = srd[1];
            s0[0] += r0.x; s0[1] += r0.y; s0[2] += r0.z; s0[3] += r0.w;
            s1[0] += r1.x; s1[1] += r1.y; s1[2] += r1.z; s1[3] += r1.w;

            float v00 = tanhf(s0[0] + Pv00.x);
            float v01 = tanhf(s0[1] + Pv00.y);
            float v10 = tanhf(s0[2] + Pv10.x);
            float v11 = tanhf(s0[3] + Pv10.y);
            float w00 = tanhf(s1[0] + Pv01.x);
            float w01 = tanhf(s1[1] + Pv01.y);
            float w10 = tanhf(s1[2] + Pv11.x);
            float w11 = tanhf(s1[3] + Pv11.y);

            const size_t i0 = (size_t)mr0 * H_ + cc0;
            const size_t i1 = (size_t)mr1 * H_ + cc0;
            *(float2*)&ox[i0]     = make_float2(v00, v01);
            *(float2*)&ox[i0 + 8] = make_float2(w00, w01);
            *(float2*)&ox[i1]     = make_float2(v10, v11);
            *(float2*)&ox[i1 + 8] = make_float2(w10, w11);

            #pragma unroll
            for (int e = 0; e < 4; e++) {
                float x0 = (e == 0) ? v00 : (e == 1) ? w00 : (e == 2) ? v10 : w10;
                float x1 = (e == 0) ? v01 : (e == 1) ? w01 : (e == 2) ? v11 : w11;
                size_t ix = (e < 2) ? (i0 + (e & 1) * 8) : (i1 + (e & 1) * 8);
                __nv_bfloat16 hh0 = __float2bfloat16_rn(x0);
                __nv_bfloat16 hh1 = __float2bfloat16_rn(x1);
                *(__nv_bfloat162*)&nhi[ix] = __nv_bfloat162{hh0, hh1};
                *(__nv_bfloat162*)&nlo[ix] = __nv_bfloat162{
                    __float2bfloat16_rn(x0 - __bfloat162float(hh0)),
                    __float2bfloat16_rn(x1 - __bfloat162float(hh1))};
            }
            if (t == T_ - 1) {
                *(float2*)&hn[i0]     = make_float2(v00, v01);
                *(float2*)&hn[i0 + 8] = make_float2(w00, w01);
                *(float2*)&hn[i1]     = make_float2(v10, v11);
                *(float2*)&hn[i1 + 8] = make_float2(w10, w11);
            }
        }
        if (t < T_ - 1) half_barrier(half);
    }
}

// ---------------------------------------------------------------------------
// Launch: per layer: split X, split W_ih, HMMA GEMM, recurrence.
// 16 graph nodes total.
// ---------------------------------------------------------------------------
extern "C" void kernel_launch(void* const* d_in, const int* in_sizes, int n_in,
                              void* d_out, int out_size)
{
    const float* inputs = (const float*)d_in[0];   // [T,B,H]
    const float* hxs    = (const float*)d_in[1];   // [L,B,H]
    const float* W_ih   = (const float*)d_in[2];   // [L,H,H]
    const float* b_ih   = (const float*)d_in[3];   // [L,H]
    const float* W_hh   = (const float*)d_in[4];   // [L,H,H]
    const float* b_hh   = (const float*)d_in[5];   // [L,H]

    float* out  = (float*)d_out;
    float* outx = out;                               // [T,B,H]
    float* outh = out + (size_t)T_ * B_ * H_;        // [L,B,H]

    static bool attr_done = false;
    if (!attr_done) {
        cudaFuncSetAttribute(rnn_seq_mma3,
                             cudaFuncAttributeMaxDynamicSharedMemorySize,
                             RNN3_SMEM);
        attr_done = true;
    }

    __nv_bfloat16* xhi; cudaGetSymbolAddress((void**)&xhi, g_Xhi);
    __nv_bfloat16* xlo; cudaGetSymbolAddress((void**)&xlo, g_Xlo);
    __nv_bfloat16* whi; cudaGetSymbolAddress((void**)&whi, g_Whi);
    __nv_bfloat16* wlo; cudaGetSymbolAddress((void**)&wlo, g_Wlo);

    const int nX4 = MTOT * H_ / 4;
    const int nW4 = H_ * H_ / 4;

    dim3 pre_grid(H_ / 128, MTOT / 128);             // (8, 256)

    for (int l = 0; l < L_; l++) {
        const float* x_l = (l == 0) ? inputs : outx;
        split_bf16<<<nX4 / 256, 256>>>(x_l, xhi, xlo, nX4);
        split_bf16<<<nW4 / 256, 256>>>(W_ih + (size_t)l * H_ * H_, whi, wlo, nW4);
        gemm_pre_bf16<<<pre_grid, 256>>>(b_ih + (size_t)l * H_,
                                         b_hh + (size_t)l * H_);
        rnn_seq_mma3<<<NBLK, NTHR, RNN3_SMEM>>>(
            hxs + (size_t)l * B_ * H_,
            W_hh + (size_t)l * H_ * H_,
            outx,
            outh + (size_t)l * B_ * H_);
    }
}